// round 16
// baseline (speedup 1.0000x reference)
#include <cuda_runtime.h>
#include <cuda_fp16.h>
#include <math.h>
#include <stdint.h>

#define B_  2
#define N_  2048
#define C_  1024
#define H_  16
#define DH_ 64
#define M_  (B_*N_)
#define BH_ (B_*H_)

// Packed fp16 planes. u32 = {f16 k_even | f16 k_odd<<16}.
// A-sides single-plane (one-sided 2-pass); B-sides (hi,lo).
__device__ uint32_t g_xh [M_ * 512];                             // x (A)
__device__ uint32_t g_wqh[3 * C_ * 512],  g_wql[3 * C_ * 512];   // qkv_w (B)
__device__ uint32_t g_wph[C_ * 512],      g_wpl[C_ * 512];       // proj_w (B)
__device__ uint32_t g_qh [BH_ * N_ * 32];                        // q /8 (A)
__device__ uint32_t g_kh [BH_ * N_ * 32], g_kl [BH_ * N_ * 32];  // k (B)
__device__ uint32_t g_aoh[M_ * 512];                             // attn out (A)
__device__ uint32_t g_v  [BH_ * N_ * 32];                        // v (fp16x2)

__constant__ float c_invf[16] = {
    1.0f, 0.7498942093324559f, 0.5623413251903491f, 0.4216965034285822f,
    0.31622776601683794f, 0.23713737056616552f, 0.1778279410038923f,
    0.13335214321633237f, 0.1f, 0.07498942093324558f, 0.05623413251903491f,
    0.04216965034285822f, 0.031622776601683794f, 0.023713737056616552f,
    0.01778279410038923f, 0.013335214321633237f
};

__device__ __forceinline__ uint32_t f16x2(float x0, float x1) {   // lo=x0, hi=x1
    uint32_t p;
    asm("cvt.rn.f16x2.f32 %0, %1, %2;" : "=r"(p) : "f"(x1), "f"(x0));
    return p;
}
__device__ __forceinline__ uint2 split_f16x2(float x0, float x1) {
    uint32_t hp;
    asm("cvt.rn.f16x2.f32 %0, %1, %2;" : "=r"(hp) : "f"(x1), "f"(x0));
    __half2 h = *(__half2*)&hp;
    float l0 = x0 - __low2float(h), l1 = x1 - __high2float(h);
    uint32_t lp;
    asm("cvt.rn.f16x2.f32 %0, %1, %2;" : "=r"(lp) : "f"(l1), "f"(l0));
    return make_uint2(hp, lp);
}
__device__ __forceinline__ void mma16f(float* d, const uint32_t* a, const uint32_t* b) {
    asm volatile(
        "mma.sync.aligned.m16n8k16.row.col.f32.f16.f16.f32 "
        "{%0,%1,%2,%3}, {%4,%5,%6,%7}, {%8,%9}, {%0,%1,%2,%3};"
        : "+f"(d[0]), "+f"(d[1]), "+f"(d[2]), "+f"(d[3])
        : "r"(a[0]), "r"(a[1]), "r"(a[2]), "r"(a[3]), "r"(b[0]), "r"(b[1]));
}
__device__ __forceinline__ void ldsm4(uint32_t* d, uint32_t a) {
    asm volatile("ldmatrix.sync.aligned.m8n8.x4.shared.b16 {%0,%1,%2,%3}, [%4];"
        : "=r"(d[0]), "=r"(d[1]), "=r"(d[2]), "=r"(d[3]) : "r"(a));
}
__device__ __forceinline__ void ldsm4t(uint32_t* d, uint32_t a) {
    asm volatile("ldmatrix.sync.aligned.m8n8.x4.trans.shared.b16 {%0,%1,%2,%3}, [%4];"
        : "=r"(d[0]), "=r"(d[1]), "=r"(d[2]), "=r"(d[3]) : "r"(a));
}
__device__ __forceinline__ uint32_t smem_u32(const void* p) {
    uint32_t a;
    asm("{ .reg .u64 t; cvta.to.shared.u64 t, %1; cvt.u32.u64 %0, t; }"
        : "=r"(a) : "l"(p));
    return a;
}
__device__ __forceinline__ void cpa16(uint32_t dst, const void* src) {
    asm volatile("cp.async.ca.shared.global [%0], [%1], 16;" :: "r"(dst), "l"(src));
}
#define CP_COMMIT() asm volatile("cp.async.commit_group;" ::: "memory")
#define CP_WAIT0()  asm volatile("cp.async.wait_group 0;" ::: "memory")
#define CP_WAIT1()  asm volatile("cp.async.wait_group 1;" ::: "memory")

// ---------------------------------------------------------------------------
__global__ __launch_bounds__(256) void splitw_kernel(
    const float4* __restrict__ src, uint32_t* __restrict__ dh,
    uint32_t* __restrict__ dl, int n4)
{
    int i = blockIdx.x * blockDim.x + threadIdx.x;
    if (i < n4) {
        float4 v = src[i];
        uint2 p0 = split_f16x2(v.x, v.y);
        uint2 p1 = split_f16x2(v.z, v.w);
        *(uint2*)(dh + 2 * i) = make_uint2(p0.x, p1.x);
        *(uint2*)(dl + 2 * i) = make_uint2(p0.y, p1.y);
    }
}
__global__ __launch_bounds__(256) void splith_kernel(
    const float4* __restrict__ src, uint32_t* __restrict__ dh, int n4)
{
    int i = blockIdx.x * blockDim.x + threadIdx.x;
    if (i < n4) {
        float4 v = src[i];
        *(uint2*)(dh + 2 * i) = make_uint2(f16x2(v.x, v.y), f16x2(v.z, v.w));
    }
}

// ===========================================================================
// GEMM mainloop: fp16 one-sided 2-pass, 3-STAGE cp.async pipeline
// (prefetch distance 2 iterations; one commit per iteration, empty at tail).
// 256 thr = 8 warps (2m x 4n), BK=32.
// ===========================================================================
#define SG 20
#define GEMM_SMEM (3 * 3 * 128 * SG * 4)             // 92160 B

__device__ __forceinline__ void gemm_ml(
    const uint32_t* __restrict__ Ah,
    const uint32_t* __restrict__ Bh, const uint32_t* __restrict__ Bl,
    int m0, int n0, uint32_t* smu, float acc[4][4][4])
{
    uint32_t* sAh = smu;
    uint32_t* sBh = sAh + 3 * 128 * SG;
    uint32_t* sBl = sBh + 3 * 128 * SG;
    const uint32_t uAh = smem_u32(sAh), uBh = smem_u32(sBh), uBl = smem_u32(sBl);

    const int tid = threadIdx.x, lane = tid & 31, wid = tid >> 5;
    const int wm = (wid >> 2) * 64, wn = (wid & 3) * 32;
    const int mq = lane >> 3, r = lane & 7;
    const uint32_t aOff = ((wm + (mq & 1) * 8 + r) * SG + (mq >> 1) * 4) * 4;
    const uint32_t bOff = ((wn + (mq >> 1) * 8 + r) * SG + (mq & 1) * 4) * 4;

#define GPREF(IT, ST) do {                                                      \
    int _ko = (IT) * 16;                                                        \
    _Pragma("unroll")                                                           \
    for (int s = 0; s < 2; ++s) {                                               \
        int c = tid + s * 256, row = c >> 2, q = (c & 3) * 4;                   \
        cpa16(uAh + (((ST)*128*SG) + row*SG + q)*4, Ah + (size_t)(m0+row)*512 + _ko + q); \
        cpa16(uBh + (((ST)*128*SG) + row*SG + q)*4, Bh + (size_t)(n0+row)*512 + _ko + q); \
        cpa16(uBl + (((ST)*128*SG) + row*SG + q)*4, Bl + (size_t)(n0+row)*512 + _ko + q); \
    }                                                                           \
} while (0)

    GPREF(0, 0); CP_COMMIT();
    GPREF(1, 1); CP_COMMIT();

    int st = 0;
    for (int it = 0; it < 32; ++it) {
        CP_WAIT1();                 // tile `it` landed; tile it+1 still in flight
        __syncthreads();            // all warps done with stage st's previous use
        const int pf = (st == 0) ? 2 : st - 1;   // stage (it+2) % 3
        if (it + 2 < 32) GPREF(it + 2, pf);
        CP_COMMIT();                // one group per iteration (maybe empty)

        const uint32_t so = st * 128 * SG * 4;
#pragma unroll
        for (int kc = 0; kc < 2; ++kc) {
            uint32_t bh[4][2], bl[4][2];
#pragma unroll
            for (int jp = 0; jp < 2; ++jp) {
                uint32_t t[4];
                ldsm4(t, uBh + so + bOff + (jp * 16 * SG + kc * 8) * 4);
                bh[2*jp][0] = t[0]; bh[2*jp][1] = t[1];
                bh[2*jp+1][0] = t[2]; bh[2*jp+1][1] = t[3];
                ldsm4(t, uBl + so + bOff + (jp * 16 * SG + kc * 8) * 4);
                bl[2*jp][0] = t[0]; bl[2*jp][1] = t[1];
                bl[2*jp+1][0] = t[2]; bl[2*jp+1][1] = t[3];
            }
            uint32_t ah[4][4];
#pragma unroll
            for (int i = 0; i < 4; ++i)
                ldsm4(ah[i], uAh + so + aOff + (i * 16 * SG + kc * 8) * 4);
#pragma unroll
            for (int i = 0; i < 4; ++i)
#pragma unroll
                for (int j = 0; j < 4; ++j)
                    mma16f(acc[i][j], ah[i], bh[j]);
#pragma unroll
            for (int i = 0; i < 4; ++i)
#pragma unroll
                for (int j = 0; j < 4; ++j)
                    mma16f(acc[i][j], ah[i], bl[j]);
        }
        st = (st == 2) ? 0 : st + 1;
    }
#undef GPREF
}

// ---------------------------------------------------------------------------
// Kernel A: qkv GEMM + RoPE; q fp16 hi-only (/8), k fp16 (hi,lo), v fp16.
// ---------------------------------------------------------------------------
__global__ __launch_bounds__(256, 2) void qkv_mma_kernel(const int* __restrict__ pos)
{
    extern __shared__ uint32_t smu[];
    const int tid = threadIdx.x, lane = tid & 31, wid = tid >> 5;
    const int gid = lane >> 2, tig = lane & 3;
    const int wm = (wid >> 2) * 64, wn = (wid & 3) * 32;
    const int m0 = blockIdx.y * 128, n0 = blockIdx.x * 128;

    float acc[4][4][4];
#pragma unroll
    for (int i = 0; i < 4; ++i)
#pragma unroll
        for (int j = 0; j < 4; ++j)
#pragma unroll
            for (int c = 0; c < 4; ++c) acc[i][j][c] = 0.f;

    gemm_ml(g_xh, g_wqh, g_wql, m0, n0, smu, acc);

    const int which = n0 >> 10;                    // 0=q 1=k 2=v
    const int h  = (((n0 & 1023) + wn) >> 6);
    const int db = wn & 32;

#pragma unroll
    for (int i = 0; i < 4; ++i) {
        int mA = m0 + wm + i * 16 + gid;
        int mB = mA + 8;
        int rowA = ((mA >> 11) * 16 + h) * 2048 + (mA & 2047);
        int rowB = ((mB >> 11) * 16 + h) * 2048 + (mB & 2047);
        size_t bAu = (size_t)rowA * 32 + (db >> 1);
        size_t bBu = (size_t)rowB * 32 + (db >> 1);
        if (which == 2) {
#pragma unroll
            for (int j = 0; j < 4; ++j) {
                int ui = j * 4 + tig;
                g_v[bAu + ui] = f16x2(acc[i][j][0], acc[i][j][1]);
                g_v[bBu + ui] = f16x2(acc[i][j][2], acc[i][j][3]);
            }
        } else {
            int2 pA = ((const int2*)pos)[mA];
            int2 pB = ((const int2*)pos)[mB];
            float pa = db ? (float)pA.y : (float)pA.x;
            float pb = db ? (float)pB.y : (float)pB.x;
            const float sc = (which == 0) ? 0.125f : 1.f;
#pragma unroll
            for (int j = 0; j < 2; ++j) {
                int dd = j * 8 + 2 * tig;
                int ui = j * 4 + tig;
                float s0a,c0a,s1a,c1a,s0b,c0b,s1b,c1b;
                sincosf(pa * c_invf[dd],     &s0a, &c0a);
                sincosf(pa * c_invf[dd + 1], &s1a, &c1a);
                sincosf(pb * c_invf[dd],     &s0b, &c0b);
                sincosf(pb * c_invf[dd + 1], &s1b, &c1b);
                float y10 = acc[i][j][0], y20 = acc[i][j+2][0];
                float y11 = acc[i][j][1], y21 = acc[i][j+2][1];
                float a0 = (y10*c0a - y20*s0a)*sc, a1 = (y11*c1a - y21*s1a)*sc;
                float a2 = (y10*s0a + y20*c0a)*sc, a3 = (y11*s1a + y21*c1a)*sc;
                float z10 = acc[i][j][2], z20 = acc[i][j+2][2];
                float z11 = acc[i][j][3], z21 = acc[i][j+2][3];
                float b0 = (z10*c0b - z20*s0b)*sc, b1 = (z11*c1b - z21*s1b)*sc;
                float b2 = (z10*s0b + z20*c0b)*sc, b3 = (z11*s1b + z21*c1b)*sc;
                if (which == 0) {
                    g_qh[bAu + ui]     = f16x2(a0, a1);
                    g_qh[bAu + ui + 8] = f16x2(a2, a3);
                    g_qh[bBu + ui]     = f16x2(b0, b1);
                    g_qh[bBu + ui + 8] = f16x2(b2, b3);
                } else {
                    uint2 u;
                    u = split_f16x2(a0, a1); g_kh[bAu + ui]     = u.x; g_kl[bAu + ui]     = u.y;
                    u = split_f16x2(a2, a3); g_kh[bAu + ui + 8] = u.x; g_kl[bAu + ui + 8] = u.y;
                    u = split_f16x2(b0, b1); g_kh[bBu + ui]     = u.x; g_kl[bBu + ui]     = u.y;
                    u = split_f16x2(b2, b3); g_kh[bBu + ui + 8] = u.x; g_kl[bBu + ui + 8] = u.y;
                }
            }
        }
    }
}

// ---------------------------------------------------------------------------
// Kernel C: out = ao @ proj_w^T + bias. Grid (8, 32). 2 CTAs/SM.
// ---------------------------------------------------------------------------
__global__ __launch_bounds__(256, 2) void proj_mma_kernel(
    const float* __restrict__ bias, float* __restrict__ out)
{
    extern __shared__ uint32_t smu[];
    const int tid = threadIdx.x, lane = tid & 31, wid = tid >> 5;
    const int gid = lane >> 2, tig = lane & 3;
    const int wm = (wid >> 2) * 64, wn = (wid & 3) * 32;
    const int m0 = blockIdx.y * 128, n0 = blockIdx.x * 128;

    float acc[4][4][4];
#pragma unroll
    for (int i = 0; i < 4; ++i)
#pragma unroll
        for (int j = 0; j < 4; ++j)
#pragma unroll
            for (int c = 0; c < 4; ++c) acc[i][j][c] = 0.f;

    gemm_ml(g_aoh, g_wph, g_wpl, m0, n0, smu, acc);

#pragma unroll
    for (int i = 0; i < 4; ++i) {
        int mA = m0 + wm + i * 16 + gid;
#pragma unroll
        for (int j = 0; j < 4; ++j) {
            int n = n0 + wn + j * 8 + 2 * tig;
            float b0 = bias[n], b1 = bias[n + 1];
            *(float2*)(out + (size_t)mA * 1024 + n) =
                make_float2(acc[i][j][0] + b0, acc[i][j][1] + b1);
            *(float2*)(out + (size_t)(mA + 8) * 1024 + n) =
                make_float2(acc[i][j][2] + b0, acc[i][j][3] + b1);
        }
    }
}

// ---------------------------------------------------------------------------
// Kernel B: flash attention (unchanged from round 14).
// ---------------------------------------------------------------------------
#define SKU 36
#define SVU 36
#define ATTN_SMEM ((2*2*64*SKU + 64*SVU) * 4)        // 46080 B

__global__ __launch_bounds__(128, 4) void attn_mma_kernel()
{
    extern __shared__ uint32_t smu[];
    uint32_t* sKh = smu;
    uint32_t* sKl = sKh + 2 * 64 * SKU;
    uint32_t* sV  = sKl + 2 * 64 * SKU;
    const uint32_t uKh = smem_u32(sKh), uKl = smem_u32(sKl), uV = smem_u32(sV);

    const int tid = threadIdx.x, lane = tid & 31, wid = tid >> 5;
    const int gid = lane >> 2, tig = lane & 3;
    const int mq = lane >> 3, r = lane & 7;
    const int bh = blockIdx.y, q0 = blockIdx.x * 64;
    const uint32_t kOff = (((mq >> 1) * 8 + r) * SKU + (mq & 1) * 4) * 4;
    const uint32_t vOff = (((lane >> 3) & 1) * 8 + r) * SVU * 4 + ((lane >> 4) * 8) * 2;

    const uint32_t* Qh = g_qh + (size_t)(bh * 2048 + q0) * 32;
    const uint32_t* Kh = g_kh + (size_t)bh * 2048 * 32;
    const uint32_t* Kl = g_kl + (size_t)bh * 2048 * 32;
    const uint32_t* Vg = g_v  + (size_t)bh * 2048 * 32;

    uint32_t qh[4][4];
#pragma unroll
    for (int kc = 0; kc < 4; ++kc) {
#pragma unroll
        for (int e = 0; e < 4; ++e) {
            size_t a = (size_t)(wid * 16 + gid + ((e & 1) ? 8 : 0)) * 32
                     + kc * 8 + tig + ((e & 2) ? 4 : 0);
            qh[kc][e] = Qh[a];
        }
    }

#define KPREF(KV0, ST) do {                                                     \
    _Pragma("unroll")                                                           \
    for (int s = 0; s < 4; ++s) {                                               \
        int c = tid + s * 128, row = c >> 3, q = (c & 7) * 4;                   \
        cpa16(uKh + (((ST)*64*SKU) + row*SKU + q)*4, Kh + (size_t)((KV0)+row)*32 + q); \
        cpa16(uKl + (((ST)*64*SKU) + row*SKU + q)*4, Kl + (size_t)((KV0)+row)*32 + q); \
    }                                                                           \
} while (0)

    KPREF(0, 0); CP_COMMIT();

    float o[8][4];
#pragma unroll
    for (int j = 0; j < 8; ++j)
#pragma unroll
        for (int c = 0; c < 4; ++c) o[j][c] = 0.f;
    float m0r = -1e30f, m1r = -1e30f, l0 = 0.f, l1 = 0.f;

    for (int it = 0; it < 32; ++it) {
        const int kv0 = it * 64, st = it & 1;
        CP_WAIT0();
        __syncthreads();

#pragma unroll
        for (int s = 0; s < 4; ++s) {
            int c = tid + s * 128, row = c >> 3, q = (c & 7) * 4;
            cpa16(uV + (row * SVU + q) * 4, Vg + (size_t)(kv0 + row) * 32 + q);
        }
        CP_COMMIT();
        if (it + 1 < 32) { KPREF(kv0 + 64, st ^ 1); }
        CP_COMMIT();

        const uint32_t so = st * 64 * SKU * 4;
        float s8[8][4];
#pragma unroll
        for (int j = 0; j < 8; ++j)
#pragma unroll
            for (int c = 0; c < 4; ++c) s8[j][c] = 0.f;
#pragma unroll
        for (int kc = 0; kc < 4; ++kc) {
            uint32_t th[4][4], tl[4][4];
#pragma unroll
            for (int jp = 0; jp < 4; ++jp) {
                ldsm4(th[jp], uKh + so + kOff + (jp * 16 * SKU + kc * 8) * 4);
                ldsm4(tl[jp], uKl + so + kOff + (jp * 16 * SKU + kc * 8) * 4);
            }
#pragma unroll
            for (int jp = 0; jp < 4; ++jp) {
                mma16f(s8[2*jp],   qh[kc], th[jp]);
                mma16f(s8[2*jp+1], qh[kc], th[jp] + 2);
            }
#pragma unroll
            for (int jp = 0; jp < 4; ++jp) {
                mma16f(s8[2*jp],   qh[kc], tl[jp]);
                mma16f(s8[2*jp+1], qh[kc], tl[jp] + 2);
            }
        }

        CP_WAIT1();
        __syncthreads();

        float mx0 = -1e30f, mx1 = -1e30f;
#pragma unroll
        for (int j = 0; j < 8; ++j) {
            mx0 = fmaxf(mx0, fmaxf(s8[j][0], s8[j][1]));
            mx1 = fmaxf(mx1, fmaxf(s8[j][2], s8[j][3]));
        }
        mx0 = fmaxf(mx0, __shfl_xor_sync(0xffffffffu, mx0, 1));
        mx0 = fmaxf(mx0, __shfl_xor_sync(0xffffffffu, mx0, 2));
        mx1 = fmaxf(mx1, __shfl_xor_sync(0xffffffffu, mx1, 1));
        mx1 = fmaxf(mx1, __shfl_xor_sync(0xffffffffu, mx1, 2));
        float mn0 = fmaxf(m0r, mx0), mn1 = fmaxf(m1r, mx1);
        float al0 = __expf(m0r - mn0), al1 = __expf(m1r - mn1);
        m0r = mn0; m1r = mn1;
        float sum0 = 0.f, sum1 = 0.f;
#pragma unroll
        for (int j = 0; j < 8; ++j) {
            s8[j][0] = __expf(s8[j][0] - mn0); sum0 += s8[j][0];
            s8[j][1] = __expf(s8[j][1] - mn0); sum0 += s8[j][1];
            s8[j][2] = __expf(s8[j][2] - mn1); sum1 += s8[j][2];
            s8[j][3] = __expf(s8[j][3] - mn1); sum1 += s8[j][3];
        }
        sum0 += __shfl_xor_sync(0xffffffffu, sum0, 1);
        sum0 += __shfl_xor_sync(0xffffffffu, sum0, 2);
        sum1 += __shfl_xor_sync(0xffffffffu, sum1, 1);
        sum1 += __shfl_xor_sync(0xffffffffu, sum1, 2);
        l0 = l0 * al0 + sum0;
        l1 = l1 * al1 + sum1;
#pragma unroll
        for (int j = 0; j < 8; ++j) {
            o[j][0] *= al0; o[j][1] *= al0;
            o[j][2] *= al1; o[j][3] *= al1;
        }

#pragma unroll
        for (int kc = 0; kc < 4; ++kc) {
            uint32_t pa[4];
            pa[0] = f16x2(s8[2*kc][0],   s8[2*kc][1]);
            pa[1] = f16x2(s8[2*kc][2],   s8[2*kc][3]);
            pa[2] = f16x2(s8[2*kc+1][0], s8[2*kc+1][1]);
            pa[3] = f16x2(s8[2*kc+1][2], s8[2*kc+1][3]);
#pragma unroll
            for (int dp = 0; dp < 4; ++dp) {
                uint32_t t[4];
                ldsm4t(t, uV + vOff + kc * 16 * SVU * 4 + dp * 32);
                mma16f(o[2*dp],   pa, t);
                mma16f(o[2*dp+1], pa, t + 2);
            }
        }
    }
#undef KPREF

    const float linv0 = 1.f / l0, linv1 = 1.f / l1;
    const int b = bh >> 4, h = bh & 15;
    const int tok0 = q0 + wid * 16 + gid, tok1 = tok0 + 8;
    size_t b0u = (size_t)(b * 2048 + tok0) * 512 + h * 32;
    size_t b1u = (size_t)(b * 2048 + tok1) * 512 + h * 32;
#pragma unroll
    for (int j = 0; j < 8; ++j) {
        int ui = j * 4 + tig;
        g_aoh[b0u + ui] = f16x2(o[j][0] * linv0, o[j][1] * linv0);
        g_aoh[b1u + ui] = f16x2(o[j][2] * linv1, o[j][3] * linv1);
    }
}

// ---------------------------------------------------------------------------
extern "C" void kernel_launch(void* const* d_in, const int* in_sizes, int n_in,
                              void* d_out, int out_size)
{
    const float* x      = (const float*)d_in[0];
    const int*   pos    = (const int*)  d_in[1];
    const float* qkv_w  = (const float*)d_in[2];
    const float* proj_w = (const float*)d_in[3];
    const float* proj_b = (const float*)d_in[4];
    float*       out    = (float*)d_out;

    uint32_t *xh, *wqh, *wql, *wph, *wpl;
    cudaGetSymbolAddress((void**)&xh,  g_xh);
    cudaGetSymbolAddress((void**)&wqh, g_wqh);
    cudaGetSymbolAddress((void**)&wql, g_wql);
    cudaGetSymbolAddress((void**)&wph, g_wph);
    cudaGetSymbolAddress((void**)&wpl, g_wpl);

    splith_kernel<<<(M_*C_/4 + 255)/256, 256>>>((const float4*)x, xh, M_*C_/4);
    splitw_kernel<<<(3*C_*C_/4 + 255)/256, 256>>>((const float4*)qkv_w, wqh, wql, 3*C_*C_/4);
    splitw_kernel<<<(C_*C_/4 + 255)/256, 256>>>((const float4*)proj_w, wph, wpl, C_*C_/4);

    cudaFuncSetAttribute(qkv_mma_kernel,
                         cudaFuncAttributeMaxDynamicSharedMemorySize, GEMM_SMEM);
    cudaFuncSetAttribute(proj_mma_kernel,
                         cudaFuncAttributeMaxDynamicSharedMemorySize, GEMM_SMEM);
    cudaFuncSetAttribute(attn_mma_kernel,
                         cudaFuncAttributeMaxDynamicSharedMemorySize, ATTN_SMEM);

    qkv_mma_kernel<<<dim3(24, 32), 256, GEMM_SMEM>>>(pos);
    attn_mma_kernel<<<dim3(32, 32), 128, ATTN_SMEM>>>();
    proj_mma_kernel<<<dim3(8, 32), 256, GEMM_SMEM>>>(proj_b, out);
}

// round 17
// speedup vs baseline: 1.0340x; 1.0340x over previous
#include <cuda_runtime.h>
#include <cuda_fp16.h>
#include <math.h>
#include <stdint.h>

#define B_  2
#define N_  2048
#define C_  1024
#define H_  16
#define DH_ 64
#define M_  (B_*N_)
#define BH_ (B_*H_)

// Packed fp16 planes. u32 = {f16 k_even | f16 k_odd<<16}.
// A-sides single-plane (one-sided 2-pass); B-sides (hi,lo).
__device__ uint32_t g_xh [M_ * 512];                             // x (A)
__device__ uint32_t g_wqh[3 * C_ * 512],  g_wql[3 * C_ * 512];   // qkv_w (B)
__device__ uint32_t g_wph[C_ * 512],      g_wpl[C_ * 512];       // proj_w (B)
__device__ uint32_t g_qh [BH_ * N_ * 32];                        // q /8 (A)
__device__ uint32_t g_kh [BH_ * N_ * 32], g_kl [BH_ * N_ * 32];  // k (B)
__device__ uint32_t g_aoh[M_ * 512];                             // attn out (A)
__device__ uint32_t g_v  [BH_ * N_ * 32];                        // v (fp16x2)

__constant__ float c_invf[16] = {
    1.0f, 0.7498942093324559f, 0.5623413251903491f, 0.4216965034285822f,
    0.31622776601683794f, 0.23713737056616552f, 0.1778279410038923f,
    0.13335214321633237f, 0.1f, 0.07498942093324558f, 0.05623413251903491f,
    0.04216965034285822f, 0.031622776601683794f, 0.023713737056616552f,
    0.01778279410038923f, 0.013335214321633237f
};

__device__ __forceinline__ uint32_t f16x2(float x0, float x1) {   // lo=x0, hi=x1
    uint32_t p;
    asm("cvt.rn.f16x2.f32 %0, %1, %2;" : "=r"(p) : "f"(x1), "f"(x0));
    return p;
}
__device__ __forceinline__ uint2 split_f16x2(float x0, float x1) {
    uint32_t hp;
    asm("cvt.rn.f16x2.f32 %0, %1, %2;" : "=r"(hp) : "f"(x1), "f"(x0));
    __half2 h = *(__half2*)&hp;
    float l0 = x0 - __low2float(h), l1 = x1 - __high2float(h);
    uint32_t lp;
    asm("cvt.rn.f16x2.f32 %0, %1, %2;" : "=r"(lp) : "f"(l1), "f"(l0));
    return make_uint2(hp, lp);
}
__device__ __forceinline__ void mma16f(float* d, const uint32_t* a, const uint32_t* b) {
    asm volatile(
        "mma.sync.aligned.m16n8k16.row.col.f32.f16.f16.f32 "
        "{%0,%1,%2,%3}, {%4,%5,%6,%7}, {%8,%9}, {%0,%1,%2,%3};"
        : "+f"(d[0]), "+f"(d[1]), "+f"(d[2]), "+f"(d[3])
        : "r"(a[0]), "r"(a[1]), "r"(a[2]), "r"(a[3]), "r"(b[0]), "r"(b[1]));
}
__device__ __forceinline__ void ldsm4(uint32_t* d, uint32_t a) {
    asm volatile("ldmatrix.sync.aligned.m8n8.x4.shared.b16 {%0,%1,%2,%3}, [%4];"
        : "=r"(d[0]), "=r"(d[1]), "=r"(d[2]), "=r"(d[3]) : "r"(a));
}
__device__ __forceinline__ void ldsm4t(uint32_t* d, uint32_t a) {
    asm volatile("ldmatrix.sync.aligned.m8n8.x4.trans.shared.b16 {%0,%1,%2,%3}, [%4];"
        : "=r"(d[0]), "=r"(d[1]), "=r"(d[2]), "=r"(d[3]) : "r"(a));
}
__device__ __forceinline__ uint32_t smem_u32(const void* p) {
    uint32_t a;
    asm("{ .reg .u64 t; cvta.to.shared.u64 t, %1; cvt.u32.u64 %0, t; }"
        : "=r"(a) : "l"(p));
    return a;
}
__device__ __forceinline__ void cpa16(uint32_t dst, const void* src) {
    asm volatile("cp.async.ca.shared.global [%0], [%1], 16;" :: "r"(dst), "l"(src));
}
#define CP_COMMIT() asm volatile("cp.async.commit_group;" ::: "memory")
#define CP_WAIT0()  asm volatile("cp.async.wait_group 0;" ::: "memory")
#define CP_WAIT1()  asm volatile("cp.async.wait_group 1;" ::: "memory")

// ---------------------------------------------------------------------------
__global__ __launch_bounds__(256) void splitw_kernel(
    const float4* __restrict__ src, uint32_t* __restrict__ dh,
    uint32_t* __restrict__ dl, int n4)
{
    int i = blockIdx.x * blockDim.x + threadIdx.x;
    if (i < n4) {
        float4 v = src[i];
        uint2 p0 = split_f16x2(v.x, v.y);
        uint2 p1 = split_f16x2(v.z, v.w);
        *(uint2*)(dh + 2 * i) = make_uint2(p0.x, p1.x);
        *(uint2*)(dl + 2 * i) = make_uint2(p0.y, p1.y);
    }
}
__global__ __launch_bounds__(256) void splith_kernel(
    const float4* __restrict__ src, uint32_t* __restrict__ dh, int n4)
{
    int i = blockIdx.x * blockDim.x + threadIdx.x;
    if (i < n4) {
        float4 v = src[i];
        *(uint2*)(dh + 2 * i) = make_uint2(f16x2(v.x, v.y), f16x2(v.z, v.w));
    }
}

// ===========================================================================
// GEMM mainloop (exact round-14 2-stage version — known good).
// fp16 one-sided 2-pass: ah*bh + ah*bl. 256 thr (2m x 4n), BK=32.
// ===========================================================================
#define SG 20
#define GEMM_SMEM (3 * 2 * 128 * SG * 4)             // 61440 B

__device__ __forceinline__ void gemm_ml(
    const uint32_t* __restrict__ Ah,
    const uint32_t* __restrict__ Bh, const uint32_t* __restrict__ Bl,
    int m0, int n0, uint32_t* smu, float acc[4][4][4])
{
    uint32_t* sAh = smu;
    uint32_t* sBh = sAh + 2 * 128 * SG;
    uint32_t* sBl = sBh + 2 * 128 * SG;
    const uint32_t uAh = smem_u32(sAh), uBh = smem_u32(sBh), uBl = smem_u32(sBl);

    const int tid = threadIdx.x, lane = tid & 31, wid = tid >> 5;
    const int wm = (wid >> 2) * 64, wn = (wid & 3) * 32;
    const int mq = lane >> 3, r = lane & 7;
    const uint32_t aOff = ((wm + (mq & 1) * 8 + r) * SG + (mq >> 1) * 4) * 4;
    const uint32_t bOff = ((wn + (mq >> 1) * 8 + r) * SG + (mq & 1) * 4) * 4;

#define GPREF(IT, ST) do {                                                      \
    int _ko = (IT) * 16;                                                        \
    _Pragma("unroll")                                                           \
    for (int s = 0; s < 2; ++s) {                                               \
        int c = tid + s * 256, row = c >> 2, q = (c & 3) * 4;                   \
        cpa16(uAh + (((ST)*128*SG) + row*SG + q)*4, Ah + (size_t)(m0+row)*512 + _ko + q); \
        cpa16(uBh + (((ST)*128*SG) + row*SG + q)*4, Bh + (size_t)(n0+row)*512 + _ko + q); \
        cpa16(uBl + (((ST)*128*SG) + row*SG + q)*4, Bl + (size_t)(n0+row)*512 + _ko + q); \
    }                                                                           \
} while (0)

    GPREF(0, 0); CP_COMMIT();

    for (int it = 0; it < 32; ++it) {
        const int st = it & 1;
        CP_WAIT0();
        __syncthreads();
        if (it + 1 < 32) { GPREF(it + 1, st ^ 1); CP_COMMIT(); }

        const uint32_t so = st * 128 * SG * 4;
#pragma unroll
        for (int kc = 0; kc < 2; ++kc) {
            uint32_t bh[4][2], bl[4][2];
#pragma unroll
            for (int jp = 0; jp < 2; ++jp) {
                uint32_t t[4];
                ldsm4(t, uBh + so + bOff + (jp * 16 * SG + kc * 8) * 4);
                bh[2*jp][0] = t[0]; bh[2*jp][1] = t[1];
                bh[2*jp+1][0] = t[2]; bh[2*jp+1][1] = t[3];
                ldsm4(t, uBl + so + bOff + (jp * 16 * SG + kc * 8) * 4);
                bl[2*jp][0] = t[0]; bl[2*jp][1] = t[1];
                bl[2*jp+1][0] = t[2]; bl[2*jp+1][1] = t[3];
            }
            uint32_t ah[4][4];
#pragma unroll
            for (int i = 0; i < 4; ++i)
                ldsm4(ah[i], uAh + so + aOff + (i * 16 * SG + kc * 8) * 4);
#pragma unroll
            for (int i = 0; i < 4; ++i)
#pragma unroll
                for (int j = 0; j < 4; ++j)
                    mma16f(acc[i][j], ah[i], bh[j]);
#pragma unroll
            for (int i = 0; i < 4; ++i)
#pragma unroll
                for (int j = 0; j < 4; ++j)
                    mma16f(acc[i][j], ah[i], bl[j]);
        }
    }
#undef GPREF
}

// ---------------------------------------------------------------------------
// Kernel A: qkv GEMM + RoPE; q fp16 hi-only (/8), k fp16 (hi,lo), v fp16.
// ---------------------------------------------------------------------------
__global__ __launch_bounds__(256, 2) void qkv_mma_kernel(const int* __restrict__ pos)
{
    extern __shared__ uint32_t smu[];
    const int tid = threadIdx.x, lane = tid & 31, wid = tid >> 5;
    const int gid = lane >> 2, tig = lane & 3;
    const int wm = (wid >> 2) * 64, wn = (wid & 3) * 32;
    const int m0 = blockIdx.y * 128, n0 = blockIdx.x * 128;

    float acc[4][4][4];
#pragma unroll
    for (int i = 0; i < 4; ++i)
#pragma unroll
        for (int j = 0; j < 4; ++j)
#pragma unroll
            for (int c = 0; c < 4; ++c) acc[i][j][c] = 0.f;

    gemm_ml(g_xh, g_wqh, g_wql, m0, n0, smu, acc);

    const int which = n0 >> 10;                    // 0=q 1=k 2=v
    const int h  = (((n0 & 1023) + wn) >> 6);
    const int db = wn & 32;

#pragma unroll
    for (int i = 0; i < 4; ++i) {
        int mA = m0 + wm + i * 16 + gid;
        int mB = mA + 8;
        int rowA = ((mA >> 11) * 16 + h) * 2048 + (mA & 2047);
        int rowB = ((mB >> 11) * 16 + h) * 2048 + (mB & 2047);
        size_t bAu = (size_t)rowA * 32 + (db >> 1);
        size_t bBu = (size_t)rowB * 32 + (db >> 1);
        if (which == 2) {
#pragma unroll
            for (int j = 0; j < 4; ++j) {
                int ui = j * 4 + tig;
                g_v[bAu + ui] = f16x2(acc[i][j][0], acc[i][j][1]);
                g_v[bBu + ui] = f16x2(acc[i][j][2], acc[i][j][3]);
            }
        } else {
            int2 pA = ((const int2*)pos)[mA];
            int2 pB = ((const int2*)pos)[mB];
            float pa = db ? (float)pA.y : (float)pA.x;
            float pb = db ? (float)pB.y : (float)pB.x;
            const float sc = (which == 0) ? 0.125f : 1.f;
#pragma unroll
            for (int j = 0; j < 2; ++j) {
                int dd = j * 8 + 2 * tig;
                int ui = j * 4 + tig;
                float s0a,c0a,s1a,c1a,s0b,c0b,s1b,c1b;
                sincosf(pa * c_invf[dd],     &s0a, &c0a);
                sincosf(pa * c_invf[dd + 1], &s1a, &c1a);
                sincosf(pb * c_invf[dd],     &s0b, &c0b);
                sincosf(pb * c_invf[dd + 1], &s1b, &c1b);
                float y10 = acc[i][j][0], y20 = acc[i][j+2][0];
                float y11 = acc[i][j][1], y21 = acc[i][j+2][1];
                float a0 = (y10*c0a - y20*s0a)*sc, a1 = (y11*c1a - y21*s1a)*sc;
                float a2 = (y10*s0a + y20*c0a)*sc, a3 = (y11*s1a + y21*c1a)*sc;
                float z10 = acc[i][j][2], z20 = acc[i][j+2][2];
                float z11 = acc[i][j][3], z21 = acc[i][j+2][3];
                float b0 = (z10*c0b - z20*s0b)*sc, b1 = (z11*c1b - z21*s1b)*sc;
                float b2 = (z10*s0b + z20*c0b)*sc, b3 = (z11*s1b + z21*c1b)*sc;
                if (which == 0) {
                    g_qh[bAu + ui]     = f16x2(a0, a1);
                    g_qh[bAu + ui + 8] = f16x2(a2, a3);
                    g_qh[bBu + ui]     = f16x2(b0, b1);
                    g_qh[bBu + ui + 8] = f16x2(b2, b3);
                } else {
                    uint2 u;
                    u = split_f16x2(a0, a1); g_kh[bAu + ui]     = u.x; g_kl[bAu + ui]     = u.y;
                    u = split_f16x2(a2, a3); g_kh[bAu + ui + 8] = u.x; g_kl[bAu + ui + 8] = u.y;
                    u = split_f16x2(b0, b1); g_kh[bBu + ui]     = u.x; g_kl[bBu + ui]     = u.y;
                    u = split_f16x2(b2, b3); g_kh[bBu + ui + 8] = u.x; g_kl[bBu + ui + 8] = u.y;
                }
            }
        }
    }
}

// ---------------------------------------------------------------------------
// Kernel C: out = ao @ proj_w^T + bias. Grid (8, 32). 2 CTAs/SM.
// ---------------------------------------------------------------------------
__global__ __launch_bounds__(256, 2) void proj_mma_kernel(
    const float* __restrict__ bias, float* __restrict__ out)
{
    extern __shared__ uint32_t smu[];
    const int tid = threadIdx.x, lane = tid & 31, wid = tid >> 5;
    const int gid = lane >> 2, tig = lane & 3;
    const int wm = (wid >> 2) * 64, wn = (wid & 3) * 32;
    const int m0 = blockIdx.y * 128, n0 = blockIdx.x * 128;

    float acc[4][4][4];
#pragma unroll
    for (int i = 0; i < 4; ++i)
#pragma unroll
        for (int j = 0; j < 4; ++j)
#pragma unroll
            for (int c = 0; c < 4; ++c) acc[i][j][c] = 0.f;

    gemm_ml(g_aoh, g_wph, g_wpl, m0, n0, smu, acc);

#pragma unroll
    for (int i = 0; i < 4; ++i) {
        int mA = m0 + wm + i * 16 + gid;
#pragma unroll
        for (int j = 0; j < 4; ++j) {
            int n = n0 + wn + j * 8 + 2 * tig;
            float b0 = bias[n], b1 = bias[n + 1];
            *(float2*)(out + (size_t)mA * 1024 + n) =
                make_float2(acc[i][j][0] + b0, acc[i][j][1] + b1);
            *(float2*)(out + (size_t)(mA + 8) * 1024 + n) =
                make_float2(acc[i][j][2] + b0, acc[i][j][3] + b1);
        }
    }
}

// ---------------------------------------------------------------------------
// Kernel B: flash attention, Tq=128 with 256 threads (8 warps x 16 q-rows).
// K/V smem shared by 8 warps -> half the K/V streaming per unit of mma.
// Per-row math identical to round 14 (bit-identical output).
// ---------------------------------------------------------------------------
#define SKU 36
#define SVU 36
#define ATTN_SMEM ((2*2*64*SKU + 64*SVU) * 4)        // 46080 B

__global__ __launch_bounds__(256, 2) void attn_mma_kernel()
{
    extern __shared__ uint32_t smu[];
    uint32_t* sKh = smu;
    uint32_t* sKl = sKh + 2 * 64 * SKU;
    uint32_t* sV  = sKl + 2 * 64 * SKU;
    const uint32_t uKh = smem_u32(sKh), uKl = smem_u32(sKl), uV = smem_u32(sV);

    const int tid = threadIdx.x, lane = tid & 31, wid = tid >> 5;   // wid 0..7
    const int gid = lane >> 2, tig = lane & 3;
    const int mq = lane >> 3, r = lane & 7;
    const int bh = blockIdx.y, q0 = blockIdx.x * 128;
    const uint32_t kOff = (((mq >> 1) * 8 + r) * SKU + (mq & 1) * 4) * 4;
    const uint32_t vOff = (((lane >> 3) & 1) * 8 + r) * SVU * 4 + ((lane >> 4) * 8) * 2;

    const uint32_t* Qh = g_qh + (size_t)(bh * 2048 + q0) * 32;
    const uint32_t* Kh = g_kh + (size_t)bh * 2048 * 32;
    const uint32_t* Kl = g_kl + (size_t)bh * 2048 * 32;
    const uint32_t* Vg = g_v  + (size_t)bh * 2048 * 32;

    uint32_t qh[4][4];
#pragma unroll
    for (int kc = 0; kc < 4; ++kc) {
#pragma unroll
        for (int e = 0; e < 4; ++e) {
            size_t a = (size_t)(wid * 16 + gid + ((e & 1) ? 8 : 0)) * 32
                     + kc * 8 + tig + ((e & 2) ? 4 : 0);
            qh[kc][e] = Qh[a];
        }
    }

// 64 K-rows x 8 cps/row = 512 cps; 256 threads -> 2 steps per plane
#define KPREF(KV0, ST) do {                                                     \
    _Pragma("unroll")                                                           \
    for (int s = 0; s < 2; ++s) {                                               \
        int c = tid + s * 256, row = c >> 3, q = (c & 7) * 4;                   \
        cpa16(uKh + (((ST)*64*SKU) + row*SKU + q)*4, Kh + (size_t)((KV0)+row)*32 + q); \
        cpa16(uKl + (((ST)*64*SKU) + row*SKU + q)*4, Kl + (size_t)((KV0)+row)*32 + q); \
    }                                                                           \
} while (0)

    KPREF(0, 0); CP_COMMIT();

    float o[8][4];
#pragma unroll
    for (int j = 0; j < 8; ++j)
#pragma unroll
        for (int c = 0; c < 4; ++c) o[j][c] = 0.f;
    float m0r = -1e30f, m1r = -1e30f, l0 = 0.f, l1 = 0.f;

    for (int it = 0; it < 32; ++it) {
        const int kv0 = it * 64, st = it & 1;
        CP_WAIT0();
        __syncthreads();

#pragma unroll
        for (int s = 0; s < 2; ++s) {
            int c = tid + s * 256, row = c >> 3, q = (c & 7) * 4;
            cpa16(uV + (row * SVU + q) * 4, Vg + (size_t)(kv0 + row) * 32 + q);
        }
        CP_COMMIT();
        if (it + 1 < 32) { KPREF(kv0 + 64, st ^ 1); }
        CP_COMMIT();

        // S = (Q/8) K^T, fp16 2-pass pass-major
        const uint32_t so = st * 64 * SKU * 4;
        float s8[8][4];
#pragma unroll
        for (int j = 0; j < 8; ++j)
#pragma unroll
            for (int c = 0; c < 4; ++c) s8[j][c] = 0.f;
#pragma unroll
        for (int kc = 0; kc < 4; ++kc) {
            uint32_t th[4][4], tl[4][4];
#pragma unroll
            for (int jp = 0; jp < 4; ++jp) {
                ldsm4(th[jp], uKh + so + kOff + (jp * 16 * SKU + kc * 8) * 4);
                ldsm4(tl[jp], uKl + so + kOff + (jp * 16 * SKU + kc * 8) * 4);
            }
#pragma unroll
            for (int jp = 0; jp < 4; ++jp) {
                mma16f(s8[2*jp],   qh[kc], th[jp]);
                mma16f(s8[2*jp+1], qh[kc], th[jp] + 2);
            }
#pragma unroll
            for (int jp = 0; jp < 4; ++jp) {
                mma16f(s8[2*jp],   qh[kc], tl[jp]);
                mma16f(s8[2*jp+1], qh[kc], tl[jp] + 2);
            }
        }

        CP_WAIT1();
        __syncthreads();

        // online softmax (rows gid, gid+8)
        float mx0 = -1e30f, mx1 = -1e30f;
#pragma unroll
        for (int j = 0; j < 8; ++j) {
            mx0 = fmaxf(mx0, fmaxf(s8[j][0], s8[j][1]));
            mx1 = fmaxf(mx1, fmaxf(s8[j][2], s8[j][3]));
        }
        mx0 = fmaxf(mx0, __shfl_xor_sync(0xffffffffu, mx0, 1));
        mx0 = fmaxf(mx0, __shfl_xor_sync(0xffffffffu, mx0, 2));
        mx1 = fmaxf(mx1, __shfl_xor_sync(0xffffffffu, mx1, 1));
        mx1 = fmaxf(mx1, __shfl_xor_sync(0xffffffffu, mx1, 2));
        float mn0 = fmaxf(m0r, mx0), mn1 = fmaxf(m1r, mx1);
        float al0 = __expf(m0r - mn0), al1 = __expf(m1r - mn1);
        m0r = mn0; m1r = mn1;
        float sum0 = 0.f, sum1 = 0.f;
#pragma unroll
        for (int j = 0; j < 8; ++j) {
            s8[j][0] = __expf(s8[j][0] - mn0); sum0 += s8[j][0];
            s8[j][1] = __expf(s8[j][1] - mn0); sum0 += s8[j][1];
            s8[j][2] = __expf(s8[j][2] - mn1); sum1 += s8[j][2];
            s8[j][3] = __expf(s8[j][3] - mn1); sum1 += s8[j][3];
        }
        sum0 += __shfl_xor_sync(0xffffffffu, sum0, 1);
        sum0 += __shfl_xor_sync(0xffffffffu, sum0, 2);
        sum1 += __shfl_xor_sync(0xffffffffu, sum1, 1);
        sum1 += __shfl_xor_sync(0xffffffffu, sum1, 2);
        l0 = l0 * al0 + sum0;
        l1 = l1 * al1 + sum1;
#pragma unroll
        for (int j = 0; j < 8; ++j) {
            o[j][0] *= al0; o[j][1] *= al0;
            o[j][2] *= al1; o[j][3] *= al1;
        }

        // O += P V : P fp16 from registers, V via ldsm.trans
#pragma unroll
        for (int kc = 0; kc < 4; ++kc) {
            uint32_t pa[4];
            pa[0] = f16x2(s8[2*kc][0],   s8[2*kc][1]);
            pa[1] = f16x2(s8[2*kc][2],   s8[2*kc][3]);
            pa[2] = f16x2(s8[2*kc+1][0], s8[2*kc+1][1]);
            pa[3] = f16x2(s8[2*kc+1][2], s8[2*kc+1][3]);
#pragma unroll
            for (int dp = 0; dp < 4; ++dp) {
                uint32_t t[4];
                ldsm4t(t, uV + vOff + kc * 16 * SVU * 4 + dp * 32);
                mma16f(o[2*dp],   pa, t);
                mma16f(o[2*dp+1], pa, t + 2);
            }
        }
    }
#undef KPREF

    const float linv0 = 1.f / l0, linv1 = 1.f / l1;
    const int b = bh >> 4, h = bh & 15;
    const int tok0 = q0 + wid * 16 + gid, tok1 = tok0 + 8;
    size_t b0u = (size_t)(b * 2048 + tok0) * 512 + h * 32;
    size_t b1u = (size_t)(b * 2048 + tok1) * 512 + h * 32;
#pragma unroll
    for (int j = 0; j < 8; ++j) {
        int ui = j * 4 + tig;
        g_aoh[b0u + ui] = f16x2(o[j][0] * linv0, o[j][1] * linv0);
        g_aoh[b1u + ui] = f16x2(o[j][2] * linv1, o[j][3] * linv1);
    }
}

// ---------------------------------------------------------------------------
extern "C" void kernel_launch(void* const* d_in, const int* in_sizes, int n_in,
                              void* d_out, int out_size)
{
    const float* x      = (const float*)d_in[0];
    const int*   pos    = (const int*)  d_in[1];
    const float* qkv_w  = (const float*)d_in[2];
    const float* proj_w = (const float*)d_in[3];
    const float* proj_b = (const float*)d_in[4];
    float*       out    = (float*)d_out;

    uint32_t *xh, *wqh, *wql, *wph, *wpl;
    cudaGetSymbolAddress((void**)&xh,  g_xh);
    cudaGetSymbolAddress((void**)&wqh, g_wqh);
    cudaGetSymbolAddress((void**)&wql, g_wql);
    cudaGetSymbolAddress((void**)&wph, g_wph);
    cudaGetSymbolAddress((void**)&wpl, g_wpl);

    splith_kernel<<<(M_*C_/4 + 255)/256, 256>>>((const float4*)x, xh, M_*C_/4);
    splitw_kernel<<<(3*C_*C_/4 + 255)/256, 256>>>((const float4*)qkv_w, wqh, wql, 3*C_*C_/4);
    splitw_kernel<<<(C_*C_/4 + 255)/256, 256>>>((const float4*)proj_w, wph, wpl, C_*C_/4);

    cudaFuncSetAttribute(qkv_mma_kernel,
                         cudaFuncAttributeMaxDynamicSharedMemorySize, GEMM_SMEM);
    cudaFuncSetAttribute(proj_mma_kernel,
                         cudaFuncAttributeMaxDynamicSharedMemorySize, GEMM_SMEM);
    cudaFuncSetAttribute(attn_mma_kernel,
                         cudaFuncAttributeMaxDynamicSharedMemorySize, ATTN_SMEM);

    qkv_mma_kernel<<<dim3(24, 32), 256, GEMM_SMEM>>>(pos);
    attn_mma_kernel<<<dim3(16, 32), 256, ATTN_SMEM>>>();
    proj_mma_kernel<<<dim3(8, 32), 256, GEMM_SMEM>>>(proj_b, out);
}